// round 16
// baseline (speedup 1.0000x reference)
#include <cuda_runtime.h>
#include <cuda_bf16.h>
#include <cuda_fp16.h>
#include <math_constants.h>
#include <cstdint>

// Problem constants
#define B_  4
#define P_  2048
#define DIM_ 1024
#define H_  16
#define HKV_ 8
#define D_  64
#define ROWS_ (B_ * P_)          // 8192
#define QKV_N 2048               // fused q|k|v column width

// fp16 plane scratch (device globals; no allocations allowed)
__device__ __half g_x[ROWS_ * DIM_];        // x single fp16
__device__ __half g_qkv[ROWS_ * QKV_N];     // q|k|v single fp16 (q pre-scaled by EXPC)
__device__ __half g_o[ROWS_ * DIM_];        // attn out single fp16
__device__ __half g_w[DIM_ * QKV_N];        // Wq|Wk|Wv single fp16
__device__ __half g_wp[DIM_ * DIM_];        // Wp single fp16
__device__ float g_sumsq[B_ * HKV_];
__device__ int   g_cnt;
__device__ int   g_kvid[H_];

// ---------------------------------------------------------------------------
// helpers
// ---------------------------------------------------------------------------
__device__ __forceinline__ uint32_t cvt2h(float x, float y)
{
    __half2 hv = __floats2half2_rn(x, y);
    return *reinterpret_cast<uint32_t*>(&hv);
}

// pack two fp32 into half2 and take 2^x elementwise (one MUFU for two values)
__device__ __forceinline__ uint32_t exp2h2(float lo, float hi)
{
    uint32_t t, r;
    asm("cvt.rn.f16x2.f32 %0, %1, %2;" : "=r"(t) : "f"(hi), "f"(lo));
    asm("ex2.approx.f16x2 %0, %1;" : "=r"(r) : "r"(t));
    return r;
}

__device__ __forceinline__ void mma16816h(float* d, const uint32_t* a, const uint32_t* b)
{
    asm volatile(
        "mma.sync.aligned.m16n8k16.row.col.f32.f16.f16.f32 "
        "{%0,%1,%2,%3}, {%4,%5,%6,%7}, {%8,%9}, {%0,%1,%2,%3};\n"
        : "+f"(d[0]), "+f"(d[1]), "+f"(d[2]), "+f"(d[3])
        : "r"(a[0]), "r"(a[1]), "r"(a[2]), "r"(a[3]), "r"(b[0]), "r"(b[1]));
}

__device__ __forceinline__ void ldsm4(uint32_t* r, uint32_t a)
{
    asm volatile("ldmatrix.sync.aligned.m8n8.x4.shared.b16 {%0,%1,%2,%3}, [%4];"
        : "=r"(r[0]), "=r"(r[1]), "=r"(r[2]), "=r"(r[3]) : "r"(a));
}

__device__ __forceinline__ void ldsm4t(uint32_t* r, uint32_t a)
{
    asm volatile("ldmatrix.sync.aligned.m8n8.x4.trans.shared.b16 {%0,%1,%2,%3}, [%4];"
        : "=r"(r[0]), "=r"(r[1]), "=r"(r[2]), "=r"(r[3]) : "r"(a));
}

__device__ __forceinline__ uint32_t s2u(const void* p)
{
    return (uint32_t)__cvta_generic_to_shared(p);
}

__device__ __forceinline__ void cp16(uint32_t dst, const void* src)
{
    asm volatile("cp.async.cg.shared.global [%0], [%1], 16;"
        :: "r"(dst), "l"(src) : "memory");
}

__device__ __forceinline__ void cp_commit()
{
    asm volatile("cp.async.commit_group;" ::: "memory");
}

template <int N>
__device__ __forceinline__ void cp_wait()
{
    asm volatile("cp.async.wait_group %0;" :: "n"(N) : "memory");
}

#define EXPC 0.18033688011112042f   // 0.125 * log2(e): folded into q at projection

// smem addressing: 128-byte rows, XOR-swizzled 16B chunks (swizzle on row)
__device__ __forceinline__ uint32_t swzA(int row, int chunk)
{
    return (uint32_t)(row * 128 + ((chunk ^ (row & 7)) << 4));
}
// B tiles with 256B logical k-rows (2 row128s); swizzle on k
__device__ __forceinline__ uint32_t swzB(int row128, int chunk)
{
    return (uint32_t)(row128 * 128 + ((chunk ^ ((row128 >> 1) & 7)) << 4));
}

// ---------------------------------------------------------------------------
// ratios + searchsorted -> g_kvid (matches JAX semantics). Run by the LAST
// finishing k-CTA of the QKV GEMM.
// ---------------------------------------------------------------------------
__device__ void ratios_inline(const float* cache)
{
    float mags[HKV_];
    for (int h = 0; h < HKV_; h++) {
        float m = 0.f;
        for (int b = 0; b < B_; b++) m += sqrtf(g_sumsq[b * HKV_ + h]);
        mags[h] = m;
    }
    float diff[HKV_];
    float s = 0.f;
    for (int h = 0; h < HKV_; h++) { diff[h] = fabsf(cache[h] - mags[h]); s += diff[h]; }
    int r[HKV_];
    int tot = 0;
    for (int h = 0; h < HKV_; h++) { r[h] = (int)rintf(diff[h] / s * (float)H_); tot += r[h]; }
    while (tot > H_) {
        int am = 0;
        for (int h = 1; h < HKV_; h++) if (r[h] > r[am]) am = h;
        r[am]--; tot--;
    }
    while (tot < H_) {
        int am = 0;
        for (int h = 1; h < HKV_; h++) if (r[h] < r[am]) am = h;
        r[am]++; tot++;
    }
    int cum[HKV_];
    int c = 0;
    for (int h = 0; h < HKV_; h++) { c += r[h]; cum[h] = c; }
    for (int qh = 0; qh < H_; qh++) {
        int j = 0;
        while (j < HKV_ - 1 && cum[j] <= qh) j++;
        g_kvid[qh] = j;
    }
    __threadfence();
}

// ---------------------------------------------------------------------------
// Fused conversion kernel: all fp32 -> fp16 planes in ONE launch.
// ---------------------------------------------------------------------------
#define XQ  (ROWS_ * DIM_ / 4)          // 2097152
#define WQQ (DIM_ * DIM_ / 4)           // 262144
#define WKQ (DIM_ * (HKV_ * D_) / 4)    // 131072
#define NTOT (XQ + WQQ + 2 * WKQ + WQQ)

__global__ void conv_all(const float* __restrict__ x,  const float* __restrict__ Wq,
                         const float* __restrict__ Wk, const float* __restrict__ Wv,
                         const float* __restrict__ Wp)
{
    for (int i = blockIdx.x * blockDim.x + threadIdx.x; i < NTOT;
         i += gridDim.x * blockDim.x) {
        if (i < XQ) {
            float4 v = ((const float4*)x)[i];
            ((uint2*)g_x)[i] = make_uint2(cvt2h(v.x, v.y), cvt2h(v.z, v.w));
        } else if (i < XQ + WQQ) {
            int j = i - XQ;
            float4 v = ((const float4*)Wq)[j];
            int r = j >> 8, c4 = j & 255;
            ((uint2*)g_w)[r * (QKV_N / 4) + c4] = make_uint2(cvt2h(v.x, v.y), cvt2h(v.z, v.w));
        } else if (i < XQ + WQQ + WKQ) {
            int j = i - XQ - WQQ;
            float4 v = ((const float4*)Wk)[j];
            int r = j >> 7, c4 = j & 127;
            ((uint2*)g_w)[r * (QKV_N / 4) + 256 + c4] = make_uint2(cvt2h(v.x, v.y), cvt2h(v.z, v.w));
        } else if (i < XQ + WQQ + 2 * WKQ) {
            int j = i - XQ - WQQ - WKQ;
            float4 v = ((const float4*)Wv)[j];
            int r = j >> 7, c4 = j & 127;
            ((uint2*)g_w)[r * (QKV_N / 4) + 384 + c4] = make_uint2(cvt2h(v.x, v.y), cvt2h(v.z, v.w));
        } else {
            int j = i - XQ - WQQ - 2 * WKQ;
            float4 v = ((const float4*)Wp)[j];
            ((uint2*)g_wp)[j] = make_uint2(cvt2h(v.x, v.y), cvt2h(v.z, v.w));
        }
    }
}

// ---------------------------------------------------------------------------
// GEMM: C = A @ W (+bias), single fp16 operands (R12 scheduling, measured best).
// BM=128, BN=128, BK=64. cp.async 3-stage. 256 threads, warp tile 32x64.
// QKV call: q columns (bn < 1024) scaled by EXPC at fp16 conversion.
// ---------------------------------------------------------------------------
#define ST_A 16384
#define ST_W 16384
#define STG  (ST_A + ST_W)           // 32KB
#define G_SMEM (3 * STG)             // 96KB
#define K_CTAS 256

__global__ __launch_bounds__(256, 2) void gemm_cp(
    const __half* __restrict__ Ag, const __half* __restrict__ Wg,
    float* __restrict__ Cf, const float* __restrict__ bias,
    __half* __restrict__ C16,
    float* __restrict__ sumsq, const float* __restrict__ cache,
    int M, int N, int K)
{
    extern __shared__ char smem[];
    const uint32_t sb = s2u(smem);

    const int tid  = threadIdx.x;
    const int lane = tid & 31;
    const int warp = tid >> 5;
    const int g = lane >> 2;
    const int c = lane & 3;
    const int wm = warp >> 1;
    const int wn = warp & 1;
    const int bm = blockIdx.y * 128;
    const int bn = blockIdx.x * 128;

    const int amrow = (lane & 7) + ((lane >> 3) & 1) * 8;
    const int akbit = (lane >> 4) & 1;
    const int bkrow = (lane & 7) + ((lane >> 3) & 1) * 8;
    const int bnbit = (lane >> 4) & 1;

    float acc[2][8][4];
    #pragma unroll
    for (int i = 0; i < 2; i++)
        #pragma unroll
        for (int j = 0; j < 8; j++)
            #pragma unroll
            for (int r = 0; r < 4; r++) acc[i][j][r] = 0.f;

    auto ISSUE = [&](int ci, int buf) {
        const int k0 = ci * 64;
        const uint32_t base = sb + buf * STG;
        #pragma unroll
        for (int it = 0; it < 4; it++) {
            int flat = it * 256 + tid;
            int row = flat >> 3, ch = flat & 7;
            uint32_t off = swzA(row, ch);
            const size_t go = (size_t)(bm + row) * K + k0 + ch * 8;
            cp16(base + off, Ag + go);
        }
        #pragma unroll
        for (int it = 0; it < 4; it++) {
            int flat = it * 256 + tid;
            int row128 = flat >> 3, ch = flat & 7;
            int kk = row128 >> 1, nh = row128 & 1;
            uint32_t off = swzB(row128, ch);
            const size_t go = (size_t)(k0 + kk) * N + bn + nh * 64 + ch * 8;
            cp16(base + ST_A + off, Wg + go);
        }
        cp_commit();
    };

    auto COMPUTE = [&](int buf) {
        const uint32_t aB = sb + buf * STG;
        const uint32_t bB = aB + ST_A;
        #pragma unroll
        for (int ks = 0; ks < 4; ks++) {
            uint32_t af[2][4];
            #pragma unroll
            for (int i = 0; i < 2; i++) {
                int row = wm * 32 + i * 16 + amrow;
                uint32_t off = swzA(row, ks * 2 + akbit);
                ldsm4(af[i], aB + off);
            }
            #pragma unroll
            for (int jp = 0; jp < 4; jp++) {
                int row128 = 2 * (ks * 16 + bkrow) + wn;
                uint32_t off = swzB(row128, jp * 2 + bnbit);
                uint32_t bh[4];
                ldsm4t(bh, bB + off);
                #pragma unroll
                for (int i = 0; i < 2; i++) {
                    mma16816h(acc[i][2 * jp],     af[i], bh);
                    mma16816h(acc[i][2 * jp + 1], af[i], bh + 2);
                }
            }
        }
    };

    const int NC = K / 64;
    ISSUE(0, 0);
    ISSUE(1, 1);

    for (int ci = 0; ci < NC; ci++) {
        if (ci + 1 < NC) cp_wait<1>(); else cp_wait<0>();
        __syncthreads();
        if (ci + 2 < NC) ISSUE(ci + 2, (ci + 2) % 3);
        COMPUTE(ci % 3);
    }

    // Epilogue (q columns of the fused QKV output get the EXPC scale)
    const float qs = (sumsq && bn < 1024) ? EXPC : 1.0f;
    #pragma unroll
    for (int i = 0; i < 2; i++) {
        int row = bm + wm * 32 + i * 16 + g;
        #pragma unroll
        for (int j = 0; j < 8; j++) {
            int col = bn + wn * 64 + j * 8 + c * 2;
            if (Cf) {
                float bx = 0.f, by = 0.f;
                if (bias) { float2 bb = *(const float2*)&bias[col]; bx = bb.x; by = bb.y; }
                *(float2*)&Cf[(size_t)row * N + col] =
                    make_float2(acc[i][j][0] + bx, acc[i][j][1] + by);
                *(float2*)&Cf[(size_t)(row + 8) * N + col] =
                    make_float2(acc[i][j][2] + bx, acc[i][j][3] + by);
            } else {
                *(uint32_t*)&C16[(size_t)row * N + col] =
                    cvt2h(acc[i][j][0] * qs, acc[i][j][1] * qs);
                *(uint32_t*)&C16[(size_t)(row + 8) * N + col] =
                    cvt2h(acc[i][j][2] * qs, acc[i][j][3] * qs);
            }
        }
    }

    // Fused sumsq over k columns (cols 1024..1535 of the fused QKV output)
    if (sumsq && bn >= 1024 && bn < 1536) {
        float loc = 0.f;
        #pragma unroll
        for (int i = 0; i < 2; i++)
            #pragma unroll
            for (int j = 0; j < 8; j++)
                #pragma unroll
                for (int r = 0; r < 4; r++) loc += acc[i][j][r] * acc[i][j][r];
        #pragma unroll
        for (int o = 16; o > 0; o >>= 1)
            loc += __shfl_xor_sync(0xffffffffu, loc, o);
        const int hkv = ((bn - 1024) >> 6) + wn;
        const int bb = bm >> 11;
        if (lane == 0) atomicAdd(&sumsq[bb * HKV_ + hkv], loc);
        __syncthreads();
        if (tid == 0) {
            __threadfence();
            if (atomicAdd(&g_cnt, 1) == K_CTAS - 1)
                ratios_inline(cache);
        }
    }
}

// ---------------------------------------------------------------------------
// Flash attention: 256 q-rows/CTA, 32 q-rows/warp (2 m-subtiles) so each K/V
// fragment feeds 4 MMAs (halves LDSM traffic per MMA). 64-kpos tiles processed
// in two 32-kpos halves to bound live registers. fp16x2 softmax, ones-MMA sums.
// ---------------------------------------------------------------------------
#define QT_ 256                         // q rows per CTA
#define ST_T 8192                       // bytes per plane per stage
#define STA  (2 * ST_T)                 // K, V = 16KB
#define A_SMEM (3 * STA)                // 48KB

__global__ __launch_bounds__(256) void attn_cp()
{
    extern __shared__ char smem[];
    const uint32_t sb = s2u(smem);

    const int qt = blockIdx.x;
    const int h  = blockIdx.y;
    const int b  = blockIdx.z;
    const int tid  = threadIdx.x;
    const int lane = tid & 31;
    const int warp = tid >> 5;
    const int g = lane >> 2;
    const int c = lane & 3;

    const int knrow = (lane & 7) + ((lane >> 4) & 1) * 8;
    const int kbit  = (lane >> 3) & 1;
    const int vkrow = (lane & 7) + ((lane >> 3) & 1) * 8;
    const int vbit  = (lane >> 4) & 1;

    const int hkv = g_kvid[h];
    const size_t kbaseg = (size_t)b * P_ * QKV_N + 1024 + hkv * D_;
    const size_t vbaseg = (size_t)b * P_ * QKV_N + 1536 + hkv * D_;

    auto ISSUE = [&](int kt, int buf) {
        const uint32_t base = sb + buf * STA;
        #pragma unroll
        for (int it = 0; it < 2; it++) {
            int flat = it * 256 + tid;          // 0..511
            int row = flat >> 3, ch = flat & 7;
            uint32_t off = swzA(row, ch);
            const size_t ro = (size_t)(kt * 64 + row) * QKV_N + ch * 8;
            cp16(base + off,        g_qkv + kbaseg + ro);
            cp16(base + ST_T + off, g_qkv + vbaseg + ro);
        }
        cp_commit();
    };

    // Q fragments: 32 rows/warp = 2 m-subtiles (EXPC already folded in)
    uint32_t qf[4][2][4];
    {
        const size_t qbase = ((size_t)b * P_ + qt * QT_ + warp * 32) * QKV_N + h * 64;
        #pragma unroll
        for (int ks = 0; ks < 4; ks++) {
            int d0 = ks * 16 + c * 2;
            #pragma unroll
            for (int i = 0; i < 2; i++) {
                size_t o0 = qbase + (size_t)(i * 16 + g) * QKV_N + d0;
                size_t o1 = qbase + (size_t)(i * 16 + g + 8) * QKV_N + d0;
                qf[ks][i][0] = *(const uint32_t*)&g_qkv[o0];
                qf[ks][i][1] = *(const uint32_t*)&g_qkv[o1];
                qf[ks][i][2] = *(const uint32_t*)&g_qkv[o0 + 8];
                qf[ks][i][3] = *(const uint32_t*)&g_qkv[o1 + 8];
            }
        }
    }

    float oacc[2][8][4];
    #pragma unroll
    for (int i = 0; i < 2; i++)
        #pragma unroll
        for (int j = 0; j < 8; j++)
            #pragma unroll
            for (int r = 0; r < 4; r++) oacc[i][j][r] = 0.f;
    float lacc[2][4];
    #pragma unroll
    for (int i = 0; i < 2; i++)
        #pragma unroll
        for (int r = 0; r < 4; r++) lacc[i][r] = 0.f;
    const uint32_t ones2[2] = {0x3C003C00u, 0x3C003C00u};

    const int NT = P_ / 64;
    ISSUE(0, 0);
    ISSUE(1, 1);

    for (int kt = 0; kt < NT; kt++) {
        if (kt + 1 < NT) cp_wait<1>(); else cp_wait<0>();
        __syncthreads();
        if (kt + 2 < NT) ISSUE(kt + 2, (kt + 2) % 3);

        const uint32_t khB = sb + (kt % 3) * STA;
        const uint32_t vhB = khB + ST_T;

        // Two 32-kpos halves
        #pragma unroll
        for (int hf = 0; hf < 2; hf++) {
            // S = Q K^T for this half
            float sacc[2][4][4];
            #pragma unroll
            for (int i = 0; i < 2; i++)
                #pragma unroll
                for (int j = 0; j < 4; j++)
                    #pragma unroll
                    for (int r = 0; r < 4; r++) sacc[i][j][r] = 0.f;
            #pragma unroll
            for (int ks = 0; ks < 4; ks++) {
                #pragma unroll
                for (int jp = 0; jp < 2; jp++) {
                    int row = hf * 32 + jp * 16 + knrow;
                    uint32_t bh[4];
                    ldsm4(bh, khB + swzA(row, ks * 2 + kbit));
                    #pragma unroll
                    for (int i = 0; i < 2; i++) {
                        mma16816h(sacc[i][2 * jp],     qf[ks][i], bh);
                        mma16816h(sacc[i][2 * jp + 1], qf[ks][i], bh + 2);
                    }
                }
            }

            // p = 2^s (fp16x2), output IS the fp16 P fragment
            uint32_t pf[2][2][4];
            #pragma unroll
            for (int i = 0; i < 2; i++)
                #pragma unroll
                for (int kf = 0; kf < 2; kf++) {
                    pf[i][kf][0] = exp2h2(sacc[i][2 * kf][0],     sacc[i][2 * kf][1]);
                    pf[i][kf][1] = exp2h2(sacc[i][2 * kf][2],     sacc[i][2 * kf][3]);
                    pf[i][kf][2] = exp2h2(sacc[i][2 * kf + 1][0], sacc[i][2 * kf + 1][1]);
                    pf[i][kf][3] = exp2h2(sacc[i][2 * kf + 1][2], sacc[i][2 * kf + 1][3]);
                }

            // Row sums: lacc += P @ ones
            #pragma unroll
            for (int i = 0; i < 2; i++)
                #pragma unroll
                for (int kf = 0; kf < 2; kf++)
                    mma16816h(lacc[i], pf[i][kf], ones2);

            // O += P V
            #pragma unroll
            for (int kf = 0; kf < 2; kf++) {
                #pragma unroll
                for (int jp = 0; jp < 4; jp++) {
                    int row = hf * 32 + kf * 16 + vkrow;
                    uint32_t vh[4];
                    ldsm4t(vh, vhB + swzA(row, jp * 2 + vbit));
                    #pragma unroll
                    for (int i = 0; i < 2; i++) {
                        mma16816h(oacc[i][2 * jp],     pf[i][kf], vh);
                        mma16816h(oacc[i][2 * jp + 1], pf[i][kf], vh + 2);
                    }
                }
            }
        }
    }

    // Epilogue: normalize, store single fp16 (feeds final GEMM)
    const size_t obase = ((size_t)b * P_ + qt * QT_ + warp * 32) * DIM_ + h * 64;
    #pragma unroll
    for (int i = 0; i < 2; i++) {
        float inv0 = 1.0f / lacc[i][0];
        float inv1 = 1.0f / lacc[i][2];
        #pragma unroll
        for (int j = 0; j < 8; j++) {
            int col = j * 8 + c * 2;
            size_t o0 = obase + (size_t)(i * 16 + g) * DIM_ + col;
            size_t o1 = obase + (size_t)(i * 16 + g + 8) * DIM_ + col;
            *(uint32_t*)&g_o[o0] = cvt2h(oacc[i][j][0] * inv0, oacc[i][j][1] * inv0);
            *(uint32_t*)&g_o[o1] = cvt2h(oacc[i][j][2] * inv1, oacc[i][j][3] * inv1);
        }
    }
}

// ---------------------------------------------------------------------------
// Launcher
// ---------------------------------------------------------------------------
extern "C" void kernel_launch(void* const* d_in, const int* in_sizes, int n_in,
                              void* d_out, int out_size)
{
    const float* x     = (const float*)d_in[0];
    const float* Wq    = (const float*)d_in[1];
    const float* Wk    = (const float*)d_in[2];
    const float* Wv    = (const float*)d_in[3];
    const float* Wp    = (const float*)d_in[4];
    const float* bp    = (const float*)d_in[5];
    const float* cache = (const float*)d_in[6];
    float* out = (float*)d_out;

    __half *xp, *qkv, *o, *w, *wp;
    float* sumsq;
    int* cnt;
    cudaGetSymbolAddress((void**)&xp, g_x);
    cudaGetSymbolAddress((void**)&qkv, g_qkv);
    cudaGetSymbolAddress((void**)&o, g_o);
    cudaGetSymbolAddress((void**)&w, g_w);
    cudaGetSymbolAddress((void**)&wp, g_wp);
    cudaGetSymbolAddress((void**)&sumsq, g_sumsq);
    cudaGetSymbolAddress((void**)&cnt, g_cnt);

    cudaFuncSetAttribute(gemm_cp, cudaFuncAttributeMaxDynamicSharedMemorySize, G_SMEM);
    cudaFuncSetAttribute(attn_cp, cudaFuncAttributeMaxDynamicSharedMemorySize, A_SMEM);

    dim3 blk(256);

    // All conversions in one launch; zero sumsq + counter
    conv_all<<<1480, 256>>>(x, Wq, Wk, Wv, Wp);
    cudaMemsetAsync(sumsq, 0, B_ * HKV_ * sizeof(float));
    cudaMemsetAsync(cnt, 0, sizeof(int));

    // Fused QKV projection + fused sumsq + last-CTA ratios (q scaled by EXPC)
    gemm_cp<<<dim3(QKV_N / 128, ROWS_ / 128), blk, G_SMEM>>>(
        xp, w, nullptr, nullptr, qkv, sumsq, cache, ROWS_, QKV_N, DIM_);

    // Attention (256 q-rows/CTA, 32 q-rows/warp)
    attn_cp<<<dim3(P_ / QT_, H_, B_), blk, A_SMEM>>>();

    // Output projection + bias (fp32 out)
    gemm_cp<<<dim3(DIM_ / 128, ROWS_ / 128), blk, G_SMEM>>>(
        o, wp, out, bp, nullptr, nullptr, nullptr, ROWS_, DIM_, DIM_);
}

// round 17
// speedup vs baseline: 1.0679x; 1.0679x over previous
#include <cuda_runtime.h>
#include <cuda_bf16.h>
#include <cuda_fp16.h>
#include <math_constants.h>
#include <cstdint>

// Problem constants
#define B_  4
#define P_  2048
#define DIM_ 1024
#define H_  16
#define HKV_ 8
#define D_  64
#define ROWS_ (B_ * P_)          // 8192
#define QKV_N 2048               // fused q|k|v column width

// fp16 plane scratch (device globals; no allocations allowed)
__device__ __half g_x[ROWS_ * DIM_];        // x single fp16
__device__ __half g_qkv[ROWS_ * QKV_N];     // q|k|v single fp16 (q pre-scaled by EXPC)
__device__ __half g_o[ROWS_ * DIM_];        // attn out single fp16
__device__ __half g_w[DIM_ * QKV_N];        // Wq|Wk|Wv single fp16
__device__ __half g_wp[DIM_ * DIM_];        // Wp single fp16
__device__ float g_sumsq[B_ * HKV_];
__device__ int   g_cnt;
__device__ int   g_kvid[H_];

// ---------------------------------------------------------------------------
// helpers
// ---------------------------------------------------------------------------
__device__ __forceinline__ uint32_t cvt2h(float x, float y)
{
    __half2 hv = __floats2half2_rn(x, y);
    return *reinterpret_cast<uint32_t*>(&hv);
}

// pack two fp32 into half2 and take 2^x elementwise (one MUFU for two values)
__device__ __forceinline__ uint32_t exp2h2(float lo, float hi)
{
    uint32_t t, r;
    asm("cvt.rn.f16x2.f32 %0, %1, %2;" : "=r"(t) : "f"(hi), "f"(lo));
    asm("ex2.approx.f16x2 %0, %1;" : "=r"(r) : "r"(t));
    return r;
}

__device__ __forceinline__ void mma16816h(float* d, const uint32_t* a, const uint32_t* b)
{
    asm volatile(
        "mma.sync.aligned.m16n8k16.row.col.f32.f16.f16.f32 "
        "{%0,%1,%2,%3}, {%4,%5,%6,%7}, {%8,%9}, {%0,%1,%2,%3};\n"
        : "+f"(d[0]), "+f"(d[1]), "+f"(d[2]), "+f"(d[3])
        : "r"(a[0]), "r"(a[1]), "r"(a[2]), "r"(a[3]), "r"(b[0]), "r"(b[1]));
}

__device__ __forceinline__ void ldsm4(uint32_t* r, uint32_t a)
{
    asm volatile("ldmatrix.sync.aligned.m8n8.x4.shared.b16 {%0,%1,%2,%3}, [%4];"
        : "=r"(r[0]), "=r"(r[1]), "=r"(r[2]), "=r"(r[3]) : "r"(a));
}

__device__ __forceinline__ void ldsm4t(uint32_t* r, uint32_t a)
{
    asm volatile("ldmatrix.sync.aligned.m8n8.x4.trans.shared.b16 {%0,%1,%2,%3}, [%4];"
        : "=r"(r[0]), "=r"(r[1]), "=r"(r[2]), "=r"(r[3]) : "r"(a));
}

__device__ __forceinline__ uint32_t s2u(const void* p)
{
    return (uint32_t)__cvta_generic_to_shared(p);
}

__device__ __forceinline__ void cp16(uint32_t dst, const void* src)
{
    asm volatile("cp.async.cg.shared.global [%0], [%1], 16;"
        :: "r"(dst), "l"(src) : "memory");
}

__device__ __forceinline__ void cp_commit()
{
    asm volatile("cp.async.commit_group;" ::: "memory");
}

template <int N>
__device__ __forceinline__ void cp_wait()
{
    asm volatile("cp.async.wait_group %0;" :: "n"(N) : "memory");
}

#define EXPC 0.18033688011112042f   // 0.125 * log2(e): folded into q at projection

// smem addressing: 128-byte rows, XOR-swizzled 16B chunks (swizzle on row)
__device__ __forceinline__ uint32_t swzA(int row, int chunk)
{
    return (uint32_t)(row * 128 + ((chunk ^ (row & 7)) << 4));
}
// B tiles with 256B logical k-rows (2 row128s); swizzle on k
__device__ __forceinline__ uint32_t swzB(int row128, int chunk)
{
    return (uint32_t)(row128 * 128 + ((chunk ^ ((row128 >> 1) & 7)) << 4));
}

// ---------------------------------------------------------------------------
// ratios + searchsorted -> g_kvid (matches JAX semantics). Run by the LAST
// finishing k-CTA of the QKV GEMM.
// ---------------------------------------------------------------------------
__device__ void ratios_inline(const float* cache)
{
    float mags[HKV_];
    for (int h = 0; h < HKV_; h++) {
        float m = 0.f;
        for (int b = 0; b < B_; b++) m += sqrtf(g_sumsq[b * HKV_ + h]);
        mags[h] = m;
    }
    float diff[HKV_];
    float s = 0.f;
    for (int h = 0; h < HKV_; h++) { diff[h] = fabsf(cache[h] - mags[h]); s += diff[h]; }
    int r[HKV_];
    int tot = 0;
    for (int h = 0; h < HKV_; h++) { r[h] = (int)rintf(diff[h] / s * (float)H_); tot += r[h]; }
    while (tot > H_) {
        int am = 0;
        for (int h = 1; h < HKV_; h++) if (r[h] > r[am]) am = h;
        r[am]--; tot--;
    }
    while (tot < H_) {
        int am = 0;
        for (int h = 1; h < HKV_; h++) if (r[h] < r[am]) am = h;
        r[am]++; tot++;
    }
    int cum[HKV_];
    int c = 0;
    for (int h = 0; h < HKV_; h++) { c += r[h]; cum[h] = c; }
    for (int qh = 0; qh < H_; qh++) {
        int j = 0;
        while (j < HKV_ - 1 && cum[j] <= qh) j++;
        g_kvid[qh] = j;
    }
    __threadfence();
}

// ---------------------------------------------------------------------------
// Fused conversion kernel: all fp32 -> fp16 planes in ONE launch.
// ---------------------------------------------------------------------------
#define XQ  (ROWS_ * DIM_ / 4)          // 2097152
#define WQQ (DIM_ * DIM_ / 4)           // 262144
#define WKQ (DIM_ * (HKV_ * D_) / 4)    // 131072
#define NTOT (XQ + WQQ + 2 * WKQ + WQQ)

__global__ void conv_all(const float* __restrict__ x,  const float* __restrict__ Wq,
                         const float* __restrict__ Wk, const float* __restrict__ Wv,
                         const float* __restrict__ Wp)
{
    for (int i = blockIdx.x * blockDim.x + threadIdx.x; i < NTOT;
         i += gridDim.x * blockDim.x) {
        if (i < XQ) {
            float4 v = ((const float4*)x)[i];
            ((uint2*)g_x)[i] = make_uint2(cvt2h(v.x, v.y), cvt2h(v.z, v.w));
        } else if (i < XQ + WQQ) {
            int j = i - XQ;
            float4 v = ((const float4*)Wq)[j];
            int r = j >> 8, c4 = j & 255;
            ((uint2*)g_w)[r * (QKV_N / 4) + c4] = make_uint2(cvt2h(v.x, v.y), cvt2h(v.z, v.w));
        } else if (i < XQ + WQQ + WKQ) {
            int j = i - XQ - WQQ;
            float4 v = ((const float4*)Wk)[j];
            int r = j >> 7, c4 = j & 127;
            ((uint2*)g_w)[r * (QKV_N / 4) + 256 + c4] = make_uint2(cvt2h(v.x, v.y), cvt2h(v.z, v.w));
        } else if (i < XQ + WQQ + 2 * WKQ) {
            int j = i - XQ - WQQ - WKQ;
            float4 v = ((const float4*)Wv)[j];
            int r = j >> 7, c4 = j & 127;
            ((uint2*)g_w)[r * (QKV_N / 4) + 384 + c4] = make_uint2(cvt2h(v.x, v.y), cvt2h(v.z, v.w));
        } else {
            int j = i - XQ - WQQ - 2 * WKQ;
            float4 v = ((const float4*)Wp)[j];
            ((uint2*)g_wp)[j] = make_uint2(cvt2h(v.x, v.y), cvt2h(v.z, v.w));
        }
    }
}

// ---------------------------------------------------------------------------
// GEMM: C = A @ W (+bias), single fp16 operands (R12 scheduling, measured best).
// BM=128, BN=128, BK=64. cp.async 3-stage. 256 threads, warp tile 32x64.
// QKV call: q columns (bn < 1024) scaled by EXPC at fp16 conversion.
// ---------------------------------------------------------------------------
#define ST_A 16384
#define ST_W 16384
#define STG  (ST_A + ST_W)           // 32KB
#define G_SMEM (3 * STG)             // 96KB
#define K_CTAS 256

__global__ __launch_bounds__(256, 2) void gemm_cp(
    const __half* __restrict__ Ag, const __half* __restrict__ Wg,
    float* __restrict__ Cf, const float* __restrict__ bias,
    __half* __restrict__ C16,
    float* __restrict__ sumsq, const float* __restrict__ cache,
    int M, int N, int K)
{
    extern __shared__ char smem[];
    const uint32_t sb = s2u(smem);

    const int tid  = threadIdx.x;
    const int lane = tid & 31;
    const int warp = tid >> 5;
    const int g = lane >> 2;
    const int c = lane & 3;
    const int wm = warp >> 1;
    const int wn = warp & 1;
    const int bm = blockIdx.y * 128;
    const int bn = blockIdx.x * 128;

    const int amrow = (lane & 7) + ((lane >> 3) & 1) * 8;
    const int akbit = (lane >> 4) & 1;
    const int bkrow = (lane & 7) + ((lane >> 3) & 1) * 8;
    const int bnbit = (lane >> 4) & 1;

    float acc[2][8][4];
    #pragma unroll
    for (int i = 0; i < 2; i++)
        #pragma unroll
        for (int j = 0; j < 8; j++)
            #pragma unroll
            for (int r = 0; r < 4; r++) acc[i][j][r] = 0.f;

    auto ISSUE = [&](int ci, int buf) {
        const int k0 = ci * 64;
        const uint32_t base = sb + buf * STG;
        #pragma unroll
        for (int it = 0; it < 4; it++) {
            int flat = it * 256 + tid;
            int row = flat >> 3, ch = flat & 7;
            uint32_t off = swzA(row, ch);
            const size_t go = (size_t)(bm + row) * K + k0 + ch * 8;
            cp16(base + off, Ag + go);
        }
        #pragma unroll
        for (int it = 0; it < 4; it++) {
            int flat = it * 256 + tid;
            int row128 = flat >> 3, ch = flat & 7;
            int kk = row128 >> 1, nh = row128 & 1;
            uint32_t off = swzB(row128, ch);
            const size_t go = (size_t)(k0 + kk) * N + bn + nh * 64 + ch * 8;
            cp16(base + ST_A + off, Wg + go);
        }
        cp_commit();
    };

    auto COMPUTE = [&](int buf) {
        const uint32_t aB = sb + buf * STG;
        const uint32_t bB = aB + ST_A;
        #pragma unroll
        for (int ks = 0; ks < 4; ks++) {
            uint32_t af[2][4];
            #pragma unroll
            for (int i = 0; i < 2; i++) {
                int row = wm * 32 + i * 16 + amrow;
                uint32_t off = swzA(row, ks * 2 + akbit);
                ldsm4(af[i], aB + off);
            }
            #pragma unroll
            for (int jp = 0; jp < 4; jp++) {
                int row128 = 2 * (ks * 16 + bkrow) + wn;
                uint32_t off = swzB(row128, jp * 2 + bnbit);
                uint32_t bh[4];
                ldsm4t(bh, bB + off);
                #pragma unroll
                for (int i = 0; i < 2; i++) {
                    mma16816h(acc[i][2 * jp],     af[i], bh);
                    mma16816h(acc[i][2 * jp + 1], af[i], bh + 2);
                }
            }
        }
    };

    const int NC = K / 64;
    ISSUE(0, 0);
    ISSUE(1, 1);

    for (int ci = 0; ci < NC; ci++) {
        if (ci + 1 < NC) cp_wait<1>(); else cp_wait<0>();
        __syncthreads();
        if (ci + 2 < NC) ISSUE(ci + 2, (ci + 2) % 3);
        COMPUTE(ci % 3);
    }

    // Epilogue (q columns of the fused QKV output get the EXPC scale)
    const float qs = (sumsq && bn < 1024) ? EXPC : 1.0f;
    #pragma unroll
    for (int i = 0; i < 2; i++) {
        int row = bm + wm * 32 + i * 16 + g;
        #pragma unroll
        for (int j = 0; j < 8; j++) {
            int col = bn + wn * 64 + j * 8 + c * 2;
            if (Cf) {
                float bx = 0.f, by = 0.f;
                if (bias) { float2 bb = *(const float2*)&bias[col]; bx = bb.x; by = bb.y; }
                *(float2*)&Cf[(size_t)row * N + col] =
                    make_float2(acc[i][j][0] + bx, acc[i][j][1] + by);
                *(float2*)&Cf[(size_t)(row + 8) * N + col] =
                    make_float2(acc[i][j][2] + bx, acc[i][j][3] + by);
            } else {
                *(uint32_t*)&C16[(size_t)row * N + col] =
                    cvt2h(acc[i][j][0] * qs, acc[i][j][1] * qs);
                *(uint32_t*)&C16[(size_t)(row + 8) * N + col] =
                    cvt2h(acc[i][j][2] * qs, acc[i][j][3] * qs);
            }
        }
    }

    // Fused sumsq over k columns (cols 1024..1535 of the fused QKV output)
    if (sumsq && bn >= 1024 && bn < 1536) {
        float loc = 0.f;
        #pragma unroll
        for (int i = 0; i < 2; i++)
            #pragma unroll
            for (int j = 0; j < 8; j++)
                #pragma unroll
                for (int r = 0; r < 4; r++) loc += acc[i][j][r] * acc[i][j][r];
        #pragma unroll
        for (int o = 16; o > 0; o >>= 1)
            loc += __shfl_xor_sync(0xffffffffu, loc, o);
        const int hkv = ((bn - 1024) >> 6) + wn;
        const int bb = bm >> 11;
        if (lane == 0) atomicAdd(&sumsq[bb * HKV_ + hkv], loc);
        __syncthreads();
        if (tid == 0) {
            __threadfence();
            if (atomicAdd(&g_cnt, 1) == K_CTAS - 1)
                ratios_inline(cache);
        }
    }
}

// ---------------------------------------------------------------------------
// Flash attention (R15 shape: 128 q-rows/CTA, 16 rows/warp) with a 4-stage
// smem ring processing TWO kv-tiles per barrier (halves bar.sync + wait count).
// fp16x2 softmax, ones-MMA row sums.
// ---------------------------------------------------------------------------
#define ST_T 8192                       // bytes per plane per stage
#define STA  (2 * ST_T)                 // K, V = 16KB
#define A_SMEM (4 * STA)                // 64KB (4 stages)

__global__ __launch_bounds__(256, 2) void attn_cp()
{
    extern __shared__ char smem[];
    const uint32_t sb = s2u(smem);

    const int qt = blockIdx.x;
    const int h  = blockIdx.y;
    const int b  = blockIdx.z;
    const int tid  = threadIdx.x;
    const int lane = tid & 31;
    const int warp = tid >> 5;
    const int g = lane >> 2;
    const int c = lane & 3;

    const int knrow = (lane & 7) + ((lane >> 4) & 1) * 8;
    const int kbit  = (lane >> 3) & 1;
    const int vkrow = (lane & 7) + ((lane >> 3) & 1) * 8;
    const int vbit  = (lane >> 4) & 1;

    const int hkv = g_kvid[h];
    const size_t kbaseg = (size_t)b * P_ * QKV_N + 1024 + hkv * D_;
    const size_t vbaseg = (size_t)b * P_ * QKV_N + 1536 + hkv * D_;

    auto ISSUE = [&](int kt, int buf) {
        const uint32_t base = sb + buf * STA;
        #pragma unroll
        for (int it = 0; it < 2; it++) {
            int flat = it * 256 + tid;          // 0..511
            int row = flat >> 3, ch = flat & 7;
            uint32_t off = swzA(row, ch);
            const size_t ro = (size_t)(kt * 64 + row) * QKV_N + ch * 8;
            cp16(base + off,        g_qkv + kbaseg + ro);
            cp16(base + ST_T + off, g_qkv + vbaseg + ro);
        }
        cp_commit();
    };

    // Q fragments (single fp16; EXPC already folded in)
    uint32_t qf[4][4];
    {
        const size_t qbase = ((size_t)b * P_ + qt * 128 + warp * 16) * QKV_N + h * 64;
        #pragma unroll
        for (int ks = 0; ks < 4; ks++) {
            int d0 = ks * 16 + c * 2;
            size_t o0 = qbase + (size_t)g * QKV_N + d0;
            size_t o1 = qbase + (size_t)(g + 8) * QKV_N + d0;
            qf[ks][0] = *(const uint32_t*)&g_qkv[o0];
            qf[ks][1] = *(const uint32_t*)&g_qkv[o1];
            qf[ks][2] = *(const uint32_t*)&g_qkv[o0 + 8];
            qf[ks][3] = *(const uint32_t*)&g_qkv[o1 + 8];
        }
    }

    float oacc[8][4];
    #pragma unroll
    for (int j = 0; j < 8; j++)
        #pragma unroll
        for (int r = 0; r < 4; r++) oacc[j][r] = 0.f;
    float lacc[4] = {0.f, 0.f, 0.f, 0.f};           // row sums via ones-MMA
    const uint32_t ones2[2] = {0x3C003C00u, 0x3C003C00u};

    // one kv-tile body
    auto TILE = [&](int buf) {
        const uint32_t khB = sb + buf * STA;
        const uint32_t vhB = khB + ST_T;

        float sacc[8][4];
        #pragma unroll
        for (int j = 0; j < 8; j++)
            #pragma unroll
            for (int r = 0; r < 4; r++) sacc[j][r] = 0.f;
        #pragma unroll
        for (int ks = 0; ks < 4; ks++) {
            #pragma unroll
            for (int jp = 0; jp < 4; jp++) {
                int row = jp * 16 + knrow;
                uint32_t bh[4];
                ldsm4(bh, khB + swzA(row, ks * 2 + kbit));
                mma16816h(sacc[2 * jp],     qf[ks], bh);
                mma16816h(sacc[2 * jp + 1], qf[ks], bh + 2);
            }
        }

        uint32_t pf[4][4];
        #pragma unroll
        for (int kf = 0; kf < 4; kf++) {
            pf[kf][0] = exp2h2(sacc[2 * kf][0],     sacc[2 * kf][1]);
            pf[kf][1] = exp2h2(sacc[2 * kf][2],     sacc[2 * kf][3]);
            pf[kf][2] = exp2h2(sacc[2 * kf + 1][0], sacc[2 * kf + 1][1]);
            pf[kf][3] = exp2h2(sacc[2 * kf + 1][2], sacc[2 * kf + 1][3]);
        }

        #pragma unroll
        for (int kf = 0; kf < 4; kf++)
            mma16816h(lacc, pf[kf], ones2);

        #pragma unroll
        for (int kf = 0; kf < 4; kf++) {
            #pragma unroll
            for (int jp = 0; jp < 4; jp++) {
                int row = kf * 16 + vkrow;
                uint32_t vh[4];
                ldsm4t(vh, vhB + swzA(row, jp * 2 + vbit));
                mma16816h(oacc[2 * jp],     pf[kf], vh);
                mma16816h(oacc[2 * jp + 1], pf[kf], vh + 2);
            }
        }
    };

    const int NT = P_ / 64;                 // 32 tiles, processed 2 per barrier
    ISSUE(0, 0);
    ISSUE(1, 1);

    for (int kt = 0; kt < NT; kt += 2) {
        cp_wait<0>();                       // tiles kt, kt+1 arrived
        __syncthreads();                    // all warps done with bufs being overwritten
        if (kt + 2 < NT) ISSUE(kt + 2, (kt + 2) & 3);
        if (kt + 3 < NT) ISSUE(kt + 3, (kt + 3) & 3);
        TILE(kt & 3);
        TILE((kt + 1) & 3);
    }

    // Epilogue: normalize, store single fp16 (feeds final GEMM)
    float inv0 = 1.0f / lacc[0];
    float inv1 = 1.0f / lacc[2];
    const size_t obase = ((size_t)b * P_ + qt * 128 + warp * 16) * DIM_ + h * 64;
    #pragma unroll
    for (int j = 0; j < 8; j++) {
        int col = j * 8 + c * 2;
        size_t o0 = obase + (size_t)g * DIM_ + col;
        size_t o1 = obase + (size_t)(g + 8) * DIM_ + col;
        *(uint32_t*)&g_o[o0] = cvt2h(oacc[j][0] * inv0, oacc[j][1] * inv0);
        *(uint32_t*)&g_o[o1] = cvt2h(oacc[j][2] * inv1, oacc[j][3] * inv1);
    }
}

// ---------------------------------------------------------------------------
// Launcher
// ---------------------------------------------------------------------------
extern "C" void kernel_launch(void* const* d_in, const int* in_sizes, int n_in,
                              void* d_out, int out_size)
{
    const float* x     = (const float*)d_in[0];
    const float* Wq    = (const float*)d_in[1];
    const float* Wk    = (const float*)d_in[2];
    const float* Wv    = (const float*)d_in[3];
    const float* Wp    = (const float*)d_in[4];
    const float* bp    = (const float*)d_in[5];
    const float* cache = (const float*)d_in[6];
    float* out = (float*)d_out;

    __half *xp, *qkv, *o, *w, *wp;
    float* sumsq;
    int* cnt;
    cudaGetSymbolAddress((void**)&xp, g_x);
    cudaGetSymbolAddress((void**)&qkv, g_qkv);
    cudaGetSymbolAddress((void**)&o, g_o);
    cudaGetSymbolAddress((void**)&w, g_w);
    cudaGetSymbolAddress((void**)&wp, g_wp);
    cudaGetSymbolAddress((void**)&sumsq, g_sumsq);
    cudaGetSymbolAddress((void**)&cnt, g_cnt);

    cudaFuncSetAttribute(gemm_cp, cudaFuncAttributeMaxDynamicSharedMemorySize, G_SMEM);
    cudaFuncSetAttribute(attn_cp, cudaFuncAttributeMaxDynamicSharedMemorySize, A_SMEM);

    dim3 blk(256);

    // All conversions in one launch; zero sumsq + counter
    conv_all<<<1480, 256>>>(x, Wq, Wk, Wv, Wp);
    cudaMemsetAsync(sumsq, 0, B_ * HKV_ * sizeof(float));
    cudaMemsetAsync(cnt, 0, sizeof(int));

    // Fused QKV projection + fused sumsq + last-CTA ratios (q scaled by EXPC)
    gemm_cp<<<dim3(QKV_N / 128, ROWS_ / 128), blk, G_SMEM>>>(
        xp, w, nullptr, nullptr, qkv, sumsq, cache, ROWS_, QKV_N, DIM_);

    // Attention (R15 shape, 2 tiles per barrier)
    attn_cp<<<dim3(P_ / 128, H_, B_), blk, A_SMEM>>>();

    // Output projection + bias (fp32 out)
    gemm_cp<<<dim3(DIM_ / 128, ROWS_ / 128), blk, G_SMEM>>>(
        o, wp, out, bp, nullptr, nullptr, nullptr, ROWS_, DIM_, DIM_);
}